// round 1
// baseline (speedup 1.0000x reference)
#include <cuda_runtime.h>
#include <math.h>

// Problem constants
#define Bb  4
#define Ss  2048
#define Hh  16
#define DHd 64
#define Dd  1024   // H*DH

// Scratch: Q/K/V projection outputs (static device globals; no runtime allocs)
__device__ float g_Q[Bb * Ss * Dd];
__device__ float g_K[Bb * Ss * Dd];
__device__ float g_V[Bb * Ss * Dd];

// ============================================================================
// GEMM: C[M,N] = A[M,K] * W[K,N] + bias[N]
// 128x128x16 tile, 256 threads, 8x8 micro-tile, float4 global loads.
// ============================================================================
#define GBM 128
#define GBN 128
#define GBK 16

__global__ __launch_bounds__(256) void gemm_bias_kernel(
    const float* __restrict__ A, const float* __restrict__ W,
    const float* __restrict__ bias, float* __restrict__ C,
    int M, int N, int K)
{
    __shared__ float As[GBK][GBM];   // A tile stored transposed: As[k][m]
    __shared__ float Bs[GBK][GBN];   // W tile: Bs[k][n]

    const int tid = threadIdx.x;
    const int tx = tid & 15;         // 0..15 -> 8 cols each
    const int ty = tid >> 4;         // 0..15 -> 8 rows each
    const int m0 = blockIdx.y * GBM;
    const int n0 = blockIdx.x * GBN;

    // Load mapping
    const int arow = tid >> 2;           // 0..63 (two halves: +0, +64)
    const int acol = (tid & 3) << 2;     // 0,4,8,12
    const int brow = tid >> 5;           // 0..7 (two halves: +0, +8)
    const int bcol = (tid & 31) << 2;    // 0..124

    float acc[8][8];
#pragma unroll
    for (int i = 0; i < 8; i++)
#pragma unroll
        for (int j = 0; j < 8; j++) acc[i][j] = 0.0f;

    for (int k0 = 0; k0 < K; k0 += GBK) {
        float4 a0 = *(const float4*)(A + (size_t)(m0 + arow) * K + k0 + acol);
        float4 a1 = *(const float4*)(A + (size_t)(m0 + arow + 64) * K + k0 + acol);
        float4 b0 = *(const float4*)(W + (size_t)(k0 + brow) * N + n0 + bcol);
        float4 b1 = *(const float4*)(W + (size_t)(k0 + brow + 8) * N + n0 + bcol);

        __syncthreads();   // previous iteration's reads complete before overwrite

        As[acol + 0][arow] = a0.x; As[acol + 1][arow] = a0.y;
        As[acol + 2][arow] = a0.z; As[acol + 3][arow] = a0.w;
        As[acol + 0][arow + 64] = a1.x; As[acol + 1][arow + 64] = a1.y;
        As[acol + 2][arow + 64] = a1.z; As[acol + 3][arow + 64] = a1.w;
        *(float4*)&Bs[brow][bcol]     = b0;
        *(float4*)&Bs[brow + 8][bcol] = b1;

        __syncthreads();

#pragma unroll
        for (int kk = 0; kk < GBK; kk++) {
            float ra[8], rb[8];
            *(float4*)(ra + 0) = *(const float4*)&As[kk][ty * 8 + 0];
            *(float4*)(ra + 4) = *(const float4*)&As[kk][ty * 8 + 4];
            *(float4*)(rb + 0) = *(const float4*)&Bs[kk][tx * 8 + 0];
            *(float4*)(rb + 4) = *(const float4*)&Bs[kk][tx * 8 + 4];
#pragma unroll
            for (int i = 0; i < 8; i++)
#pragma unroll
                for (int j = 0; j < 8; j++)
                    acc[i][j] = fmaf(ra[i], rb[j], acc[i][j]);
        }
    }

    // Epilogue: add bias, vectorized store
    float bb[8];
#pragma unroll
    for (int j = 0; j < 8; j++) bb[j] = bias[n0 + tx * 8 + j];

#pragma unroll
    for (int i = 0; i < 8; i++) {
        float* cp = C + (size_t)(m0 + ty * 8 + i) * N + n0 + tx * 8;
        float4 v0, v1;
        v0.x = acc[i][0] + bb[0]; v0.y = acc[i][1] + bb[1];
        v0.z = acc[i][2] + bb[2]; v0.w = acc[i][3] + bb[3];
        v1.x = acc[i][4] + bb[4]; v1.y = acc[i][5] + bb[5];
        v1.z = acc[i][6] + bb[6]; v1.w = acc[i][7] + bb[7];
        *(float4*)(cp + 0) = v0;
        *(float4*)(cp + 4) = v1;
    }
}

// ============================================================================
// Flash attention (fp32, online softmax).
// Per block: 128 query rows for one (b,h). Iterate 64-key tiles.
// 256 threads = 16x16; each thread: 8 q-rows x (4 keys for S-phase / 4 dims
// for O-phase). Row softmax stats reduced across the 16-lane tx group (shfl).
// ============================================================================
#define AT_BM 128
#define AT_BN 64
#define PAD   65   // 65 % 32 == 1 -> spread banks

__global__ __launch_bounds__(256) void attn_kernel(
    const float* __restrict__ gQ, const float* __restrict__ gK,
    const float* __restrict__ gV, float* __restrict__ gO)
{
    extern __shared__ float sm[];
    float* Qs = sm;                       // 128*65
    float* Ks = Qs + AT_BM * PAD;         // 64*65
    float* Vs = Ks + AT_BN * PAD;         // 64*65
    float* Ps = Vs + AT_BN * PAD;         // 128*65

    const int tid = threadIdx.x;
    const int tx = tid & 15;
    const int ty = tid >> 4;
    const int bh = blockIdx.y;
    const int b = bh >> 4;
    const int h = bh & 15;
    const int q0 = blockIdx.x * AT_BM;

    const float* Qp = gQ + ((size_t)b * Ss + q0) * Dd + h * DHd;
    const float* Kp = gK + (size_t)b * Ss * Dd + h * DHd;
    const float* Vp = gV + (size_t)b * Ss * Dd + h * DHd;

    // Load Q tile: 128 rows x 64 cols
    for (int t = tid; t < AT_BM * 16; t += 256) {
        int r = t >> 4, c = (t & 15) << 2;
        float4 v = *(const float4*)(Qp + (size_t)r * Dd + c);
        Qs[r * PAD + c + 0] = v.x; Qs[r * PAD + c + 1] = v.y;
        Qs[r * PAD + c + 2] = v.z; Qs[r * PAD + c + 3] = v.w;
    }

    float o[8][4];
    float mrow[8], lrow[8];
#pragma unroll
    for (int i = 0; i < 8; i++) {
        mrow[i] = -1e30f; lrow[i] = 0.0f;
        o[i][0] = o[i][1] = o[i][2] = o[i][3] = 0.0f;
    }

    // exponent domain: e = s * (1/sqrt(DH)) * log2(e); softmax uses 2^(e - m)
    const float Cs = 1.4426950408889634f * 0.125f;

    __syncthreads();

    for (int kt = 0; kt < Ss / AT_BN; kt++) {
        // Load K, V tiles: 64 rows x 64 cols each
        for (int t = tid; t < AT_BN * 16; t += 256) {
            int r = t >> 4, c = (t & 15) << 2;
            float4 vk = *(const float4*)(Kp + (size_t)(kt * AT_BN + r) * Dd + c);
            float4 vv = *(const float4*)(Vp + (size_t)(kt * AT_BN + r) * Dd + c);
            Ks[r * PAD + c + 0] = vk.x; Ks[r * PAD + c + 1] = vk.y;
            Ks[r * PAD + c + 2] = vk.z; Ks[r * PAD + c + 3] = vk.w;
            Vs[r * PAD + c + 0] = vv.x; Vs[r * PAD + c + 1] = vv.y;
            Vs[r * PAD + c + 2] = vv.z; Vs[r * PAD + c + 3] = vv.w;
        }
        __syncthreads();

        // S = Q * K^T  (each thread: 8 rows x 4 keys)
        float s[8][4];
#pragma unroll
        for (int i = 0; i < 8; i++)
            s[i][0] = s[i][1] = s[i][2] = s[i][3] = 0.0f;

#pragma unroll 4
        for (int d = 0; d < DHd; d++) {
            float kv0 = Ks[(tx * 4 + 0) * PAD + d];
            float kv1 = Ks[(tx * 4 + 1) * PAD + d];
            float kv2 = Ks[(tx * 4 + 2) * PAD + d];
            float kv3 = Ks[(tx * 4 + 3) * PAD + d];
#pragma unroll
            for (int i = 0; i < 8; i++) {
                float qv = Qs[(ty * 8 + i) * PAD + d];
                s[i][0] = fmaf(qv, kv0, s[i][0]);
                s[i][1] = fmaf(qv, kv1, s[i][1]);
                s[i][2] = fmaf(qv, kv2, s[i][2]);
                s[i][3] = fmaf(qv, kv3, s[i][3]);
            }
        }

        // Online softmax update + write P tile
#pragma unroll
        for (int i = 0; i < 8; i++) {
            float e0 = s[i][0] * Cs, e1 = s[i][1] * Cs;
            float e2 = s[i][2] * Cs, e3 = s[i][3] * Cs;
            float mi = fmaxf(fmaxf(e0, e1), fmaxf(e2, e3));
            mi = fmaxf(mi, __shfl_xor_sync(0xffffffffu, mi, 1));
            mi = fmaxf(mi, __shfl_xor_sync(0xffffffffu, mi, 2));
            mi = fmaxf(mi, __shfl_xor_sync(0xffffffffu, mi, 4));
            mi = fmaxf(mi, __shfl_xor_sync(0xffffffffu, mi, 8));
            float mn = fmaxf(mrow[i], mi);
            float alpha = exp2f(mrow[i] - mn);
            mrow[i] = mn;
            float p0 = exp2f(e0 - mn), p1 = exp2f(e1 - mn);
            float p2 = exp2f(e2 - mn), p3 = exp2f(e3 - mn);
            float ls = (p0 + p1) + (p2 + p3);
            ls += __shfl_xor_sync(0xffffffffu, ls, 1);
            ls += __shfl_xor_sync(0xffffffffu, ls, 2);
            ls += __shfl_xor_sync(0xffffffffu, ls, 4);
            ls += __shfl_xor_sync(0xffffffffu, ls, 8);
            lrow[i] = lrow[i] * alpha + ls;
            o[i][0] *= alpha; o[i][1] *= alpha;
            o[i][2] *= alpha; o[i][3] *= alpha;
            int r = ty * 8 + i;
            Ps[r * PAD + tx * 4 + 0] = p0;
            Ps[r * PAD + tx * 4 + 1] = p1;
            Ps[r * PAD + tx * 4 + 2] = p2;
            Ps[r * PAD + tx * 4 + 3] = p3;
        }
        __syncthreads();

        // O += P * V  (each thread: 8 rows x 4 dims, dims = tx*4..tx*4+3)
#pragma unroll 4
        for (int k = 0; k < AT_BN; k++) {
            float v0 = Vs[k * PAD + tx * 4 + 0];
            float v1 = Vs[k * PAD + tx * 4 + 1];
            float v2 = Vs[k * PAD + tx * 4 + 2];
            float v3 = Vs[k * PAD + tx * 4 + 3];
#pragma unroll
            for (int i = 0; i < 8; i++) {
                float p = Ps[(ty * 8 + i) * PAD + k];
                o[i][0] = fmaf(p, v0, o[i][0]);
                o[i][1] = fmaf(p, v1, o[i][1]);
                o[i][2] = fmaf(p, v2, o[i][2]);
                o[i][3] = fmaf(p, v3, o[i][3]);
            }
        }
        __syncthreads();   // before next tile overwrites Ks/Vs/Ps
    }

    // Write output: out[b, q0+r, h*64 + d]
    float* Op = gO + ((size_t)b * Ss + q0) * Dd + h * DHd;
#pragma unroll
    for (int i = 0; i < 8; i++) {
        float inv = 1.0f / lrow[i];
        float* row = Op + (size_t)(ty * 8 + i) * Dd + tx * 4;
        float4 v;
        v.x = o[i][0] * inv; v.y = o[i][1] * inv;
        v.z = o[i][2] * inv; v.w = o[i][3] * inv;
        *(float4*)row = v;
    }
}

// ============================================================================
// Launch
// ============================================================================
extern "C" void kernel_launch(void* const* d_in, const int* in_sizes, int n_in,
                              void* d_out, int out_size)
{
    const float* x  = (const float*)d_in[0];
    const float* Wq = (const float*)d_in[1];
    const float* bq = (const float*)d_in[2];
    const float* Wk = (const float*)d_in[3];
    const float* bk = (const float*)d_in[4];
    const float* Wv = (const float*)d_in[5];
    const float* bv = (const float*)d_in[6];
    float* out = (float*)d_out;

    void *qp, *kp, *vp;
    cudaGetSymbolAddress(&qp, g_Q);
    cudaGetSymbolAddress(&kp, g_K);
    cudaGetSymbolAddress(&vp, g_V);

    const int M = Bb * Ss;   // 8192
    const int N = Dd;        // 1024
    const int K = Dd;        // 1024

    dim3 ggrid(N / GBN, M / GBM);   // (8, 64)
    gemm_bias_kernel<<<ggrid, 256>>>(x, Wq, bq, (float*)qp, M, N, K);
    gemm_bias_kernel<<<ggrid, 256>>>(x, Wk, bk, (float*)kp, M, N, K);
    gemm_bias_kernel<<<ggrid, 256>>>(x, Wv, bv, (float*)vp, M, N, K);

    const int smem_bytes = (AT_BM * PAD + 2 * AT_BN * PAD + AT_BM * PAD) * sizeof(float);
    cudaFuncSetAttribute(attn_kernel, cudaFuncAttributeMaxDynamicSharedMemorySize, smem_bytes);
    dim3 agrid(Ss / AT_BM, Bb * Hh);   // (16, 64)
    attn_kernel<<<agrid, 256, smem_bytes>>>((const float*)qp, (const float*)kp,
                                            (const float*)vp, out);
}

// round 4
// speedup vs baseline: 2.1383x; 2.1383x over previous
#include <cuda_runtime.h>
#include <math.h>
#include <stdint.h>

// Problem constants
#define Bb  4
#define Ss  2048
#define Hh  16
#define DHd 64
#define Dd  1024   // H*DH

// Scratch: Q/K/V projection outputs
__device__ float g_Q[Bb * Ss * Dd];
__device__ float g_K[Bb * Ss * Dd];
__device__ float g_V[Bb * Ss * Dd];

// ---------------------------------------------------------------------------
// Helpers: tf32 convert + mma.m16n8k8 tf32
// ---------------------------------------------------------------------------
__device__ __forceinline__ uint32_t f2tf32(float f) {
    uint32_t u;
    asm("cvt.rna.tf32.f32 %0, %1;" : "=r"(u) : "f"(f));
    return u;
}

__device__ __forceinline__ void mma_tf32(float c[4], const uint32_t a[4], const uint32_t b[2]) {
    asm volatile(
        "mma.sync.aligned.m16n8k8.row.col.f32.tf32.tf32.f32 "
        "{%0,%1,%2,%3}, {%4,%5,%6,%7}, {%8,%9}, {%0,%1,%2,%3};\n"
        : "+f"(c[0]), "+f"(c[1]), "+f"(c[2]), "+f"(c[3])
        : "r"(a[0]), "r"(a[1]), "r"(a[2]), "r"(a[3]), "r"(b[0]), "r"(b[1]));
}

// ============================================================================
// GEMM: C[M,N] = A[M,K] * W[K,N] + bias[N]   (tf32 tensor-core)
// 128x128x32 tile, 256 threads = 8 warps (4m x 2n), warp tile 32x64.
// ============================================================================
#define TBM 128
#define TBN 128
#define TBK 32
#define ASTR (TBM + 4)   // 132: frag-load banks = 4t+g, conflict-free
#define BSTR (TBN + 4)

__global__ __launch_bounds__(256) void gemm_tf32_kernel(
    const float* __restrict__ A, const float* __restrict__ W,
    const float* __restrict__ bias, float* __restrict__ C,
    int M, int N, int K)
{
    __shared__ uint32_t As[TBK][ASTR];   // As[k][m], tf32 bits
    __shared__ uint32_t Bs[TBK][BSTR];   // Bs[k][n], tf32 bits

    const int tid  = threadIdx.x;
    const int warp = tid >> 5;
    const int lane = tid & 31;
    const int g = lane >> 2;     // 0..7
    const int t = lane & 3;      // 0..3
    const int wm = (warp >> 1) * 32;   // warp m offset within tile
    const int wn = (warp & 1) * 64;    // warp n offset within tile
    const int m0 = blockIdx.y * TBM;
    const int n0 = blockIdx.x * TBN;

    // Global-load index mapping
    const int ar = tid >> 1;           // 0..127 (A row)
    const int ac = (tid & 1) * 16;     // 0 or 16 (A k-col half)
    const int br = tid >> 3;           // 0..31  (B k-row)
    const int bc = (tid & 7) * 16;     // B n-col base

    float acc[2][8][4];
#pragma unroll
    for (int mt = 0; mt < 2; mt++)
#pragma unroll
        for (int nt = 0; nt < 8; nt++)
#pragma unroll
            for (int i = 0; i < 4; i++) acc[mt][nt][i] = 0.0f;

    for (int k0 = 0; k0 < K; k0 += TBK) {
        float4 av[4], bv[4];
#pragma unroll
        for (int j = 0; j < 4; j++) {
            av[j] = *(const float4*)(A + (size_t)(m0 + ar) * K + k0 + ac + 4 * j);
            bv[j] = *(const float4*)(W + (size_t)(k0 + br) * N + n0 + bc + 4 * j);
        }
        __syncthreads();
#pragma unroll
        for (int j = 0; j < 4; j++) {
            As[ac + 4 * j + 0][ar] = f2tf32(av[j].x);
            As[ac + 4 * j + 1][ar] = f2tf32(av[j].y);
            As[ac + 4 * j + 2][ar] = f2tf32(av[j].z);
            As[ac + 4 * j + 3][ar] = f2tf32(av[j].w);
            Bs[br][bc + 4 * j + 0] = f2tf32(bv[j].x);
            Bs[br][bc + 4 * j + 1] = f2tf32(bv[j].y);
            Bs[br][bc + 4 * j + 2] = f2tf32(bv[j].z);
            Bs[br][bc + 4 * j + 3] = f2tf32(bv[j].w);
        }
        __syncthreads();

#pragma unroll
        for (int kk = 0; kk < 4; kk++) {
            const int kb = kk * 8;
            uint32_t afr[2][4];
#pragma unroll
            for (int mt = 0; mt < 2; mt++) {
                const int mb = wm + mt * 16;
                afr[mt][0] = As[kb + t    ][mb + g];
                afr[mt][1] = As[kb + t    ][mb + g + 8];
                afr[mt][2] = As[kb + t + 4][mb + g];
                afr[mt][3] = As[kb + t + 4][mb + g + 8];
            }
            uint32_t bfr[8][2];
#pragma unroll
            for (int nt = 0; nt < 8; nt++) {
                const int nb = wn + nt * 8;
                bfr[nt][0] = Bs[kb + t    ][nb + g];
                bfr[nt][1] = Bs[kb + t + 4][nb + g];
            }
#pragma unroll
            for (int mt = 0; mt < 2; mt++)
#pragma unroll
                for (int nt = 0; nt < 8; nt++)
                    mma_tf32(acc[mt][nt], afr[mt], bfr[nt]);
        }
    }

    // Epilogue: bias + store (C-frag layout: rows g,g+8; cols 2t,2t+1)
#pragma unroll
    for (int mt = 0; mt < 2; mt++) {
        const int r0 = m0 + wm + mt * 16 + g;
#pragma unroll
        for (int nt = 0; nt < 8; nt++) {
            const int col = n0 + wn + nt * 8 + 2 * t;
            const float b0 = bias[col], b1 = bias[col + 1];
            float2 v0, v1;
            v0.x = acc[mt][nt][0] + b0; v0.y = acc[mt][nt][1] + b1;
            v1.x = acc[mt][nt][2] + b0; v1.y = acc[mt][nt][3] + b1;
            *(float2*)(C + (size_t)r0 * N + col)       = v0;
            *(float2*)(C + (size_t)(r0 + 8) * N + col) = v1;
        }
    }
}

// ============================================================================
// Flash attention with tf32 mma.
// Block: 128 q-rows for one (b,h), 256 threads = 8 warps; warp w owns
// q-rows 16w..16w+15. Iterate 64-key tiles. S and O accums in mma C-frags.
// ============================================================================
#define AT_BM 128
#define AT_BN 64
#define KPAD  68   // 64+4: frag loads hit banks 4g+t / 4t+g -> conflict-free

// SMEM (uint32 units): Ks[64][68], Vs[64][68], Ps[128][68] (also Q staging)
#define KS_OFF 0
#define VS_OFF (64 * KPAD)
#define PS_OFF (2 * 64 * KPAD)
#define AT_SMEM_U32 (2 * 64 * KPAD + 128 * KPAD)

__global__ __launch_bounds__(256) void attn_tf32_kernel(
    const float* __restrict__ gQ, const float* __restrict__ gK,
    const float* __restrict__ gV, float* __restrict__ gO)
{
    extern __shared__ uint32_t sm[];
    uint32_t* Ks = sm + KS_OFF;
    uint32_t* Vs = sm + VS_OFF;
    uint32_t* Ps = sm + PS_OFF;

    const int tid  = threadIdx.x;
    const int warp = tid >> 5;
    const int lane = tid & 31;
    const int g = lane >> 2;
    const int t = lane & 3;
    const int bh = blockIdx.y;
    const int b = bh >> 4;
    const int h = bh & 15;
    const int q0 = blockIdx.x * AT_BM;

    const float* Qp = gQ + ((size_t)b * Ss + q0) * Dd + h * DHd;
    const float* Kp = gK + (size_t)b * Ss * Dd + h * DHd;
    const float* Vp = gV + (size_t)b * Ss * Dd + h * DHd;

    // Stage Q tile (128x64) into Ps region as tf32
#pragma unroll
    for (int jj = 0; jj < 8; jj++) {
        int lin = tid + 256 * jj;            // 0..2047
        int r = lin >> 4, c = (lin & 15) * 4;
        float4 v = *(const float4*)(Qp + (size_t)r * Dd + c);
        Ps[r * KPAD + c + 0] = f2tf32(v.x);
        Ps[r * KPAD + c + 1] = f2tf32(v.y);
        Ps[r * KPAD + c + 2] = f2tf32(v.z);
        Ps[r * KPAD + c + 3] = f2tf32(v.w);
    }
    __syncthreads();

    // Load Q fragments (persist in registers); rows 16*warp + {g, g+8}
    const int r0 = 16 * warp + g;
    const int r1 = r0 + 8;
    uint32_t qa[8][4];
#pragma unroll
    for (int kk = 0; kk < 8; kk++) {
        const int kb = kk * 8;
        qa[kk][0] = Ps[r0 * KPAD + kb + t];
        qa[kk][1] = Ps[r1 * KPAD + kb + t];
        qa[kk][2] = Ps[r0 * KPAD + kb + t + 4];
        qa[kk][3] = Ps[r1 * KPAD + kb + t + 4];
    }

    float o[8][4];
#pragma unroll
    for (int nt = 0; nt < 8; nt++)
        o[nt][0] = o[nt][1] = o[nt][2] = o[nt][3] = 0.0f;
    float mr0 = -1e30f, mr1 = -1e30f, l0 = 0.0f, l1 = 0.0f;

    const float Cs = 1.4426950408889634f * 0.125f;   // log2(e)/sqrt(64)

    for (int kt = 0; kt < Ss / AT_BN; kt++) {
        // Load K,V tiles (64x64) as tf32
        {
            int r = tid >> 2, cb = (tid & 3) * 16;
            const float* kp = Kp + (size_t)(kt * AT_BN + r) * Dd + cb;
            const float* vp = Vp + (size_t)(kt * AT_BN + r) * Dd + cb;
#pragma unroll
            for (int j = 0; j < 4; j++) {
                float4 vk = *(const float4*)(kp + 4 * j);
                float4 vv = *(const float4*)(vp + 4 * j);
                int c = cb + 4 * j;
                Ks[r * KPAD + c + 0] = f2tf32(vk.x);
                Ks[r * KPAD + c + 1] = f2tf32(vk.y);
                Ks[r * KPAD + c + 2] = f2tf32(vk.z);
                Ks[r * KPAD + c + 3] = f2tf32(vk.w);
                Vs[r * KPAD + c + 0] = f2tf32(vv.x);
                Vs[r * KPAD + c + 1] = f2tf32(vv.y);
                Vs[r * KPAD + c + 2] = f2tf32(vv.z);
                Vs[r * KPAD + c + 3] = f2tf32(vv.w);
            }
        }
        __syncthreads();

        // S = Q * K^T : per warp 16 rows x 64 keys
        float s[8][4];
#pragma unroll
        for (int nt = 0; nt < 8; nt++)
            s[nt][0] = s[nt][1] = s[nt][2] = s[nt][3] = 0.0f;
#pragma unroll
        for (int kk = 0; kk < 8; kk++) {
            const int kb = kk * 8;
#pragma unroll
            for (int nt = 0; nt < 8; nt++) {
                uint32_t bfr[2];
                bfr[0] = Ks[(nt * 8 + g) * KPAD + kb + t];
                bfr[1] = Ks[(nt * 8 + g) * KPAD + kb + t + 4];
                mma_tf32(s[nt], qa[kk], bfr);
            }
        }

        // Online softmax (rows r0, r1). Quad lanes (xor 1,2) share a row.
        float mx0 = -1e30f, mx1 = -1e30f;
#pragma unroll
        for (int nt = 0; nt < 8; nt++) {
            mx0 = fmaxf(mx0, fmaxf(s[nt][0], s[nt][1]));
            mx1 = fmaxf(mx1, fmaxf(s[nt][2], s[nt][3]));
        }
        mx0 = fmaxf(mx0, __shfl_xor_sync(0xffffffffu, mx0, 1));
        mx0 = fmaxf(mx0, __shfl_xor_sync(0xffffffffu, mx0, 2));
        mx1 = fmaxf(mx1, __shfl_xor_sync(0xffffffffu, mx1, 1));
        mx1 = fmaxf(mx1, __shfl_xor_sync(0xffffffffu, mx1, 2));

        float mn0 = fmaxf(mr0, Cs * mx0);
        float mn1 = fmaxf(mr1, Cs * mx1);
        float alpha0 = exp2f(mr0 - mn0);
        float alpha1 = exp2f(mr1 - mn1);
        mr0 = mn0; mr1 = mn1;

        float ls0 = 0.0f, ls1 = 0.0f;
#pragma unroll
        for (int nt = 0; nt < 8; nt++) {
            float p0 = exp2f(s[nt][0] * Cs - mn0);
            float p1 = exp2f(s[nt][1] * Cs - mn0);
            float p2 = exp2f(s[nt][2] * Cs - mn1);
            float p3 = exp2f(s[nt][3] * Cs - mn1);
            ls0 += p0 + p1;
            ls1 += p2 + p3;
            const int col = nt * 8 + 2 * t;
            Ps[r0 * KPAD + col]     = f2tf32(p0);
            Ps[r0 * KPAD + col + 1] = f2tf32(p1);
            Ps[r1 * KPAD + col]     = f2tf32(p2);
            Ps[r1 * KPAD + col + 1] = f2tf32(p3);
        }
        ls0 += __shfl_xor_sync(0xffffffffu, ls0, 1);
        ls0 += __shfl_xor_sync(0xffffffffu, ls0, 2);
        ls1 += __shfl_xor_sync(0xffffffffu, ls1, 1);
        ls1 += __shfl_xor_sync(0xffffffffu, ls1, 2);
        l0 = l0 * alpha0 + ls0;
        l1 = l1 * alpha1 + ls1;

#pragma unroll
        for (int nt = 0; nt < 8; nt++) {
            o[nt][0] *= alpha0; o[nt][1] *= alpha0;
            o[nt][2] *= alpha1; o[nt][3] *= alpha1;
        }
        __syncthreads();   // P/V in place before PV phase

        // O += P * V : k = 64 keys, n = 64 dims
#pragma unroll
        for (int kk = 0; kk < 8; kk++) {
            const int kb = kk * 8;
            uint32_t pa[4];
            pa[0] = Ps[r0 * KPAD + kb + t];
            pa[1] = Ps[r1 * KPAD + kb + t];
            pa[2] = Ps[r0 * KPAD + kb + t + 4];
            pa[3] = Ps[r1 * KPAD + kb + t + 4];
#pragma unroll
            for (int nt = 0; nt < 8; nt++) {
                uint32_t bfr[2];
                bfr[0] = Vs[(kb + t)     * KPAD + nt * 8 + g];
                bfr[1] = Vs[(kb + t + 4) * KPAD + nt * 8 + g];
                mma_tf32(o[nt], pa, bfr);
            }
        }
        __syncthreads();   // before next iter overwrites Ks/Vs/Ps
    }

    // Output: out[b, q0+r, h*64 + col], normalized
    const float inv0 = 1.0f / l0;
    const float inv1 = 1.0f / l1;
    float* Op = gO + ((size_t)b * Ss + q0) * Dd + h * DHd;
#pragma unroll
    for (int nt = 0; nt < 8; nt++) {
        const int col = nt * 8 + 2 * t;
        float2 v0, v1;
        v0.x = o[nt][0] * inv0; v0.y = o[nt][1] * inv0;
        v1.x = o[nt][2] * inv1; v1.y = o[nt][3] * inv1;
        *(float2*)(Op + (size_t)r0 * Dd + col) = v0;
        *(float2*)(Op + (size_t)r1 * Dd + col) = v1;
    }
}

// ============================================================================
// Launch
// ============================================================================
extern "C" void kernel_launch(void* const* d_in, const int* in_sizes, int n_in,
                              void* d_out, int out_size)
{
    const float* x  = (const float*)d_in[0];
    const float* Wq = (const float*)d_in[1];
    const float* bq = (const float*)d_in[2];
    const float* Wk = (const float*)d_in[3];
    const float* bk = (const float*)d_in[4];
    const float* Wv = (const float*)d_in[5];
    const float* bv = (const float*)d_in[6];
    float* out = (float*)d_out;

    void *qp, *kp, *vp;
    cudaGetSymbolAddress(&qp, g_Q);
    cudaGetSymbolAddress(&kp, g_K);
    cudaGetSymbolAddress(&vp, g_V);

    const int M = Bb * Ss, N = Dd, K = Dd;

    dim3 ggrid(N / TBN, M / TBM);   // (8, 64)
    gemm_tf32_kernel<<<ggrid, 256>>>(x, Wq, bq, (float*)qp, M, N, K);
    gemm_tf32_kernel<<<ggrid, 256>>>(x, Wk, bk, (float*)kp, M, N, K);
    gemm_tf32_kernel<<<ggrid, 256>>>(x, Wv, bv, (float*)vp, M, N, K);

    const int smem_bytes = AT_SMEM_U32 * (int)sizeof(uint32_t);   // ~69.6 KB
    static int attr_set = 0;
    if (!attr_set) {
        cudaFuncSetAttribute(attn_tf32_kernel,
                             cudaFuncAttributeMaxDynamicSharedMemorySize, smem_bytes);
        attr_set = 1;
    }
    dim3 agrid(Ss / AT_BM, Bb * Hh);   // (16, 64)
    attn_tf32_kernel<<<agrid, 256, smem_bytes>>>((const float*)qp, (const float*)kp,
                                                 (const float*)vp, out);
}

// round 9
// speedup vs baseline: 2.1686x; 1.0142x over previous
#include <cuda_runtime.h>
#include <math.h>
#include <stdint.h>

// Problem constants
#define Bb  4
#define Ss  2048
#define Hh  16
#define DHd 64
#define Dd  1024   // H*DH

// Scratch: Q/K/V projection outputs
__device__ float g_Q[Bb * Ss * Dd];
__device__ float g_K[Bb * Ss * Dd];
__device__ float g_V[Bb * Ss * Dd];

// ---------------------------------------------------------------------------
// Helpers: tf32 convert + mma.m16n8k8 tf32
// ---------------------------------------------------------------------------
__device__ __forceinline__ uint32_t f2tf32(float f) {
    uint32_t u;
    asm("cvt.rna.tf32.f32 %0, %1;" : "=r"(u) : "f"(f));
    return u;
}

__device__ __forceinline__ void mma_tf32(float c[4], const uint32_t a[4], const uint32_t b[2]) {
    asm volatile(
        "mma.sync.aligned.m16n8k8.row.col.f32.tf32.tf32.f32 "
        "{%0,%1,%2,%3}, {%4,%5,%6,%7}, {%8,%9}, {%0,%1,%2,%3};\n"
        : "+f"(c[0]), "+f"(c[1]), "+f"(c[2]), "+f"(c[3])
        : "r"(a[0]), "r"(a[1]), "r"(a[2]), "r"(a[3]), "r"(b[0]), "r"(b[1]));
}

// ============================================================================
// GEMM: C[M,N] = A[M,K] * W[K,N] + bias[N]   (tf32, 2-stage double buffer)
// 128x128x32 tile, 256 threads = 8 warps (4m x 2n), warp tile 32x64.
// ============================================================================
#define TBM 128
#define TBN 128
#define TBK 32
#define ASTR (TBM + 4)   // 132
#define BSTR (TBN + 4)
#define ASZ (TBK * ASTR)
#define BSZ (TBK * BSTR)
#define GEMM_SMEM_BYTES ((2 * ASZ + 2 * BSZ) * 4)

__global__ __launch_bounds__(256, 2) void gemm_tf32_kernel(
    const float* __restrict__ A, const float* __restrict__ W,
    const float* __restrict__ bias, float* __restrict__ C,
    int M, int N, int K)
{
    extern __shared__ uint32_t gsm[];
    uint32_t* Asb = gsm;             // [2][TBK][ASTR]
    uint32_t* Bsb = gsm + 2 * ASZ;   // [2][TBK][BSTR]

    const int tid  = threadIdx.x;
    const int warp = tid >> 5;
    const int lane = tid & 31;
    const int g = lane >> 2;
    const int t = lane & 3;
    const int wm = (warp >> 1) * 32;
    const int wn = (warp & 1) * 64;
    const int m0 = blockIdx.y * TBM;
    const int n0 = blockIdx.x * TBN;

    const int ar = tid >> 1;           // 0..127
    const int ac = (tid & 1) * 16;     // 0 or 16
    const int br = tid >> 3;           // 0..31
    const int bc = (tid & 7) * 16;     // 0..112

    float acc[2][8][4];
#pragma unroll
    for (int mt = 0; mt < 2; mt++)
#pragma unroll
        for (int nt = 0; nt < 8; nt++)
#pragma unroll
            for (int i = 0; i < 4; i++) acc[mt][nt][i] = 0.0f;

    float4 av[4], bv[4];
    // prologue: load tile 0
#pragma unroll
    for (int j = 0; j < 4; j++) {
        av[j] = *(const float4*)(A + (size_t)(m0 + ar) * K + ac + 4 * j);
        bv[j] = *(const float4*)(W + (size_t)br * N + n0 + bc + 4 * j);
    }
#pragma unroll
    for (int j = 0; j < 4; j++) {
        Asb[(ac + 4 * j + 0) * ASTR + ar] = f2tf32(av[j].x);
        Asb[(ac + 4 * j + 1) * ASTR + ar] = f2tf32(av[j].y);
        Asb[(ac + 4 * j + 2) * ASTR + ar] = f2tf32(av[j].z);
        Asb[(ac + 4 * j + 3) * ASTR + ar] = f2tf32(av[j].w);
        Bsb[br * BSTR + bc + 4 * j + 0] = f2tf32(bv[j].x);
        Bsb[br * BSTR + bc + 4 * j + 1] = f2tf32(bv[j].y);
        Bsb[br * BSTR + bc + 4 * j + 2] = f2tf32(bv[j].z);
        Bsb[br * BSTR + bc + 4 * j + 3] = f2tf32(bv[j].w);
    }
    __syncthreads();

    int st = 0;
    for (int k0 = 0; k0 < K; k0 += TBK) {
        const bool more = (k0 + TBK) < K;
        if (more) {
#pragma unroll
            for (int j = 0; j < 4; j++) {
                av[j] = *(const float4*)(A + (size_t)(m0 + ar) * K + k0 + TBK + ac + 4 * j);
                bv[j] = *(const float4*)(W + (size_t)(k0 + TBK + br) * N + n0 + bc + 4 * j);
            }
        }

        const uint32_t* Asl = Asb + st * ASZ;
        const uint32_t* Bsl = Bsb + st * BSZ;
#pragma unroll
        for (int kk = 0; kk < 4; kk++) {
            const int kb = kk * 8;
            uint32_t afr[2][4];
#pragma unroll
            for (int mt = 0; mt < 2; mt++) {
                const int mb = wm + mt * 16;
                afr[mt][0] = Asl[(kb + t)     * ASTR + mb + g];
                afr[mt][1] = Asl[(kb + t)     * ASTR + mb + g + 8];
                afr[mt][2] = Asl[(kb + t + 4) * ASTR + mb + g];
                afr[mt][3] = Asl[(kb + t + 4) * ASTR + mb + g + 8];
            }
            uint32_t bfr[8][2];
#pragma unroll
            for (int nt = 0; nt < 8; nt++) {
                const int nb = wn + nt * 8;
                bfr[nt][0] = Bsl[(kb + t)     * BSTR + nb + g];
                bfr[nt][1] = Bsl[(kb + t + 4) * BSTR + nb + g];
            }
#pragma unroll
            for (int mt = 0; mt < 2; mt++)
#pragma unroll
                for (int nt = 0; nt < 8; nt++)
                    mma_tf32(acc[mt][nt], afr[mt], bfr[nt]);
        }

        if (more) {
            uint32_t* Asw = Asb + (st ^ 1) * ASZ;
            uint32_t* Bsw = Bsb + (st ^ 1) * BSZ;
#pragma unroll
            for (int j = 0; j < 4; j++) {
                Asw[(ac + 4 * j + 0) * ASTR + ar] = f2tf32(av[j].x);
                Asw[(ac + 4 * j + 1) * ASTR + ar] = f2tf32(av[j].y);
                Asw[(ac + 4 * j + 2) * ASTR + ar] = f2tf32(av[j].z);
                Asw[(ac + 4 * j + 3) * ASTR + ar] = f2tf32(av[j].w);
                Bsw[br * BSTR + bc + 4 * j + 0] = f2tf32(bv[j].x);
                Bsw[br * BSTR + bc + 4 * j + 1] = f2tf32(bv[j].y);
                Bsw[br * BSTR + bc + 4 * j + 2] = f2tf32(bv[j].z);
                Bsw[br * BSTR + bc + 4 * j + 3] = f2tf32(bv[j].w);
            }
        }
        __syncthreads();
        st ^= 1;
    }

    // Epilogue: bias + store
#pragma unroll
    for (int mt = 0; mt < 2; mt++) {
        const int r0 = m0 + wm + mt * 16 + g;
#pragma unroll
        for (int nt = 0; nt < 8; nt++) {
            const int col = n0 + wn + nt * 8 + 2 * t;
            const float b0 = bias[col], b1 = bias[col + 1];
            float2 v0, v1;
            v0.x = acc[mt][nt][0] + b0; v0.y = acc[mt][nt][1] + b1;
            v1.x = acc[mt][nt][2] + b0; v1.y = acc[mt][nt][3] + b1;
            *(float2*)(C + (size_t)r0 * N + col)       = v0;
            *(float2*)(C + (size_t)(r0 + 8) * N + col) = v1;
        }
    }
}

// ============================================================================
// Flash attention, tf32 mma. 128 q-rows per CTA, 4 warps x 32 rows
// (two m16 tiles per warp -> each K/V b-fragment feeds 2 mmas).
// ============================================================================
#define AT_BM 128
#define AT_BN 64
#define KPAD  68

#define KS_OFF 0
#define VS_OFF (64 * KPAD)
#define PS_OFF (2 * 64 * KPAD)
#define AT_SMEM_U32 (2 * 64 * KPAD + 128 * KPAD)

__global__ __launch_bounds__(128, 2) void attn_tf32_kernel(
    const float* __restrict__ gQ, const float* __restrict__ gK,
    const float* __restrict__ gV, float* __restrict__ gO)
{
    extern __shared__ uint32_t sm[];
    uint32_t* Ks = sm + KS_OFF;
    uint32_t* Vs = sm + VS_OFF;
    uint32_t* Ps = sm + PS_OFF;

    const int tid  = threadIdx.x;
    const int warp = tid >> 5;       // 0..3
    const int lane = tid & 31;
    const int g = lane >> 2;
    const int t = lane & 3;
    const int bh = blockIdx.y;
    const int b = bh >> 4;
    const int h = bh & 15;
    const int q0 = blockIdx.x * AT_BM;

    const float* Qp = gQ + ((size_t)b * Ss + q0) * Dd + h * DHd;
    const float* Kp = gK + (size_t)b * Ss * Dd + h * DHd;
    const float* Vp = gV + (size_t)b * Ss * Dd + h * DHd;

    // Stage Q tile (128x64) into Ps as tf32 (128 threads, 16 float4 each)
#pragma unroll
    for (int jj = 0; jj < 16; jj++) {
        int lin = tid + 128 * jj;
        int r = lin >> 4, c = (lin & 15) * 4;
        float4 v = *(const float4*)(Qp + (size_t)r * Dd + c);
        Ps[r * KPAD + c + 0] = f2tf32(v.x);
        Ps[r * KPAD + c + 1] = f2tf32(v.y);
        Ps[r * KPAD + c + 2] = f2tf32(v.z);
        Ps[r * KPAD + c + 3] = f2tf32(v.w);
    }
    __syncthreads();

    // Q fragments in registers; warp owns rows rb..rb+31 (2 m16 tiles)
    const int rb = 32 * warp;
    uint32_t qa[2][8][4];
#pragma unroll
    for (int mt = 0; mt < 2; mt++) {
        const int r0 = rb + 16 * mt + g;
        const int r1 = r0 + 8;
#pragma unroll
        for (int kk = 0; kk < 8; kk++) {
            const int kb = kk * 8;
            qa[mt][kk][0] = Ps[r0 * KPAD + kb + t];
            qa[mt][kk][1] = Ps[r1 * KPAD + kb + t];
            qa[mt][kk][2] = Ps[r0 * KPAD + kb + t + 4];
            qa[mt][kk][3] = Ps[r1 * KPAD + kb + t + 4];
        }
    }

    float o[2][8][4];
#pragma unroll
    for (int mt = 0; mt < 2; mt++)
#pragma unroll
        for (int nt = 0; nt < 8; nt++)
            o[mt][nt][0] = o[mt][nt][1] = o[mt][nt][2] = o[mt][nt][3] = 0.0f;
    float mr[2][2] = {{-1e30f, -1e30f}, {-1e30f, -1e30f}};
    float l[2][2]  = {{0.0f, 0.0f}, {0.0f, 0.0f}};

    const float Cs = 1.4426950408889634f * 0.125f;   // log2(e)/sqrt(64)

    for (int kt = 0; kt < Ss / AT_BN; kt++) {
        __syncthreads();   // all warps done reading prev Ks/Vs

        // Load K,V tiles (64x64) as tf32; 128 threads: r=tid>>1, 32-col half
        {
            int r = tid >> 1, cb = (tid & 1) * 32;
            const float* kp = Kp + (size_t)(kt * AT_BN + r) * Dd + cb;
            const float* vp = Vp + (size_t)(kt * AT_BN + r) * Dd + cb;
#pragma unroll
            for (int j = 0; j < 8; j++) {
                float4 vk = *(const float4*)(kp + 4 * j);
                float4 vv = *(const float4*)(vp + 4 * j);
                int c = cb + 4 * j;
                Ks[r * KPAD + c + 0] = f2tf32(vk.x);
                Ks[r * KPAD + c + 1] = f2tf32(vk.y);
                Ks[r * KPAD + c + 2] = f2tf32(vk.z);
                Ks[r * KPAD + c + 3] = f2tf32(vk.w);
                Vs[r * KPAD + c + 0] = f2tf32(vv.x);
                Vs[r * KPAD + c + 1] = f2tf32(vv.y);
                Vs[r * KPAD + c + 2] = f2tf32(vv.z);
                Vs[r * KPAD + c + 3] = f2tf32(vv.w);
            }
        }
        __syncthreads();

        // S = Q K^T : 32 rows x 64 keys per warp; b-frags shared across mt
        float s[2][8][4];
#pragma unroll
        for (int mt = 0; mt < 2; mt++)
#pragma unroll
            for (int nt = 0; nt < 8; nt++)
                s[mt][nt][0] = s[mt][nt][1] = s[mt][nt][2] = s[mt][nt][3] = 0.0f;
#pragma unroll
        for (int kk = 0; kk < 8; kk++) {
            const int kb = kk * 8;
#pragma unroll
            for (int nt = 0; nt < 8; nt++) {
                uint32_t bfr[2];
                bfr[0] = Ks[(nt * 8 + g) * KPAD + kb + t];
                bfr[1] = Ks[(nt * 8 + g) * KPAD + kb + t + 4];
                mma_tf32(s[0][nt], qa[0][kk], bfr);
                mma_tf32(s[1][nt], qa[1][kk], bfr);
            }
        }

        // Online softmax per m-tile; quad lanes (xor 1,2) share each row
#pragma unroll
        for (int mt = 0; mt < 2; mt++) {
            const int r0 = rb + 16 * mt + g;
            const int r1 = r0 + 8;
            float mx0 = -1e30f, mx1 = -1e30f;
#pragma unroll
            for (int nt = 0; nt < 8; nt++) {
                mx0 = fmaxf(mx0, fmaxf(s[mt][nt][0], s[mt][nt][1]));
                mx1 = fmaxf(mx1, fmaxf(s[mt][nt][2], s[mt][nt][3]));
            }
            mx0 = fmaxf(mx0, __shfl_xor_sync(0xffffffffu, mx0, 1));
            mx0 = fmaxf(mx0, __shfl_xor_sync(0xffffffffu, mx0, 2));
            mx1 = fmaxf(mx1, __shfl_xor_sync(0xffffffffu, mx1, 1));
            mx1 = fmaxf(mx1, __shfl_xor_sync(0xffffffffu, mx1, 2));

            float mn0 = fmaxf(mr[mt][0], Cs * mx0);
            float mn1 = fmaxf(mr[mt][1], Cs * mx1);
            float alpha0 = exp2f(mr[mt][0] - mn0);
            float alpha1 = exp2f(mr[mt][1] - mn1);
            mr[mt][0] = mn0; mr[mt][1] = mn1;

            float ls0 = 0.0f, ls1 = 0.0f;
#pragma unroll
            for (int nt = 0; nt < 8; nt++) {
                float p0 = exp2f(s[mt][nt][0] * Cs - mn0);
                float p1 = exp2f(s[mt][nt][1] * Cs - mn0);
                float p2 = exp2f(s[mt][nt][2] * Cs - mn1);
                float p3 = exp2f(s[mt][nt][3] * Cs - mn1);
                ls0 += p0 + p1;
                ls1 += p2 + p3;
                const int col = nt * 8 + 2 * t;
                Ps[r0 * KPAD + col]     = f2tf32(p0);
                Ps[r0 * KPAD + col + 1] = f2tf32(p1);
                Ps[r1 * KPAD + col]     = f2tf32(p2);
                Ps[r1 * KPAD + col + 1] = f2tf32(p3);
            }
            ls0 += __shfl_xor_sync(0xffffffffu, ls0, 1);
            ls0 += __shfl_xor_sync(0xffffffffu, ls0, 2);
            ls1 += __shfl_xor_sync(0xffffffffu, ls1, 1);
            ls1 += __shfl_xor_sync(0xffffffffu, ls1, 2);
            l[mt][0] = l[mt][0] * alpha0 + ls0;
            l[mt][1] = l[mt][1] * alpha1 + ls1;

#pragma unroll
            for (int nt = 0; nt < 8; nt++) {
                o[mt][nt][0] *= alpha0; o[mt][nt][1] *= alpha0;
                o[mt][nt][2] *= alpha1; o[mt][nt][3] *= alpha1;
            }
        }
        __syncwarp();   // P rows are warp-private: cross-lane STS->LDS fence only

        // O += P V : b-frags (V) shared across mt
#pragma unroll
        for (int kk = 0; kk < 8; kk++) {
            const int kb = kk * 8;
            uint32_t pa0[4], pa1[4];
            pa0[0] = Ps[(rb + g)      * KPAD + kb + t];
            pa0[1] = Ps[(rb + g + 8)  * KPAD + kb + t];
            pa0[2] = Ps[(rb + g)      * KPAD + kb + t + 4];
            pa0[3] = Ps[(rb + g + 8)  * KPAD + kb + t + 4];
            pa1[0] = Ps[(rb + 16 + g)     * KPAD + kb + t];
            pa1[1] = Ps[(rb + 16 + g + 8) * KPAD + kb + t];
            pa1[2] = Ps[(rb + 16 + g)     * KPAD + kb + t + 4];
            pa1[3] = Ps[(rb + 16 + g + 8) * KPAD + kb + t + 4];
#pragma unroll
            for (int nt = 0; nt < 8; nt++) {
                uint32_t bfr[2];
                bfr[0] = Vs[(kb + t)     * KPAD + nt * 8 + g];
                bfr[1] = Vs[(kb + t + 4) * KPAD + nt * 8 + g];
                mma_tf32(o[0][nt], pa0, bfr);
                mma_tf32(o[1][nt], pa1, bfr);
            }
        }
    }

    // Output, normalized
    float* Op = gO + ((size_t)b * Ss + q0) * Dd + h * DHd;
#pragma unroll
    for (int mt = 0; mt < 2; mt++) {
        const int r0 = rb + 16 * mt + g;
        const int r1 = r0 + 8;
        const float inv0 = 1.0f / l[mt][0];
        const float inv1 = 1.0f / l[mt][1];
#pragma unroll
        for (int nt = 0; nt < 8; nt++) {
            const int col = nt * 8 + 2 * t;
            float2 v0, v1;
            v0.x = o[mt][nt][0] * inv0; v0.y = o[mt][nt][1] * inv0;
            v1.x = o[mt][nt][2] * inv1; v1.y = o[mt][nt][3] * inv1;
            *(float2*)(Op + (size_t)r0 * Dd + col) = v0;
            *(float2*)(Op + (size_t)r1 * Dd + col) = v1;
        }
    }
}

// ============================================================================
// Launch
// ============================================================================
extern "C" void kernel_launch(void* const* d_in, const int* in_sizes, int n_in,
                              void* d_out, int out_size)
{
    const float* x  = (const float*)d_in[0];
    const float* Wq = (const float*)d_in[1];
    const float* bq = (const float*)d_in[2];
    const float* Wk = (const float*)d_in[3];
    const float* bk = (const float*)d_in[4];
    const float* Wv = (const float*)d_in[5];
    const float* bv = (const float*)d_in[6];
    float* out = (float*)d_out;

    void *qp, *kp, *vp;
    cudaGetSymbolAddress(&qp, g_Q);
    cudaGetSymbolAddress(&kp, g_K);
    cudaGetSymbolAddress(&vp, g_V);

    const int M = Bb * Ss, N = Dd, K = Dd;

    const int attn_smem = AT_SMEM_U32 * (int)sizeof(uint32_t);   // ~69.6 KB
    static int attr_set = 0;
    if (!attr_set) {
        cudaFuncSetAttribute(gemm_tf32_kernel,
                             cudaFuncAttributeMaxDynamicSharedMemorySize, GEMM_SMEM_BYTES);
        cudaFuncSetAttribute(attn_tf32_kernel,
                             cudaFuncAttributeMaxDynamicSharedMemorySize, attn_smem);
        attr_set = 1;
    }

    dim3 ggrid(N / TBN, M / TBM);   // (8, 64)
    gemm_tf32_kernel<<<ggrid, 256, GEMM_SMEM_BYTES>>>(x, Wq, bq, (float*)qp, M, N, K);
    gemm_tf32_kernel<<<ggrid, 256, GEMM_SMEM_BYTES>>>(x, Wk, bk, (float*)kp, M, N, K);
    gemm_tf32_kernel<<<ggrid, 256, GEMM_SMEM_BYTES>>>(x, Wv, bv, (float*)vp, M, N, K);

    dim3 agrid(Ss / AT_BM, Bb * Hh);   // (16, 64)
    attn_tf32_kernel<<<agrid, 128, attn_smem>>>((const float*)qp, (const float*)kp,
                                                (const float*)vp, out);
}